// round 3
// baseline (speedup 1.0000x reference)
#include <cuda_runtime.h>
#include <math_constants.h>

#define BB 2
#define NN 8192
#define SS 4096
#define IN_CH 64
#define TRANS_CH 64
#define OUT_CH 128
#define TP 8          // sampled points per block in fused kernel

// ---------------- device scratch (no cudaMalloc allowed) ----------------
__device__ float4 g_xyzw[BB * NN];      // x,y,z,|x|^2
__device__ float4 g_sxyzw[BB * SS];     // sampled gather (sample-space order)

// z-sorted copies
__device__ float4 g_pfull[BB * NN];     // full set sorted by z
__device__ float  g_zfull[BB * NN];
__device__ int    g_ofull[BB * NN];     // sorted pos -> original global id
__device__ float4 g_psamp[BB * SS];     // sampled set sorted by z
__device__ float  g_zsamp[BB * SS];
__device__ int    g_osamp[BB * SS];     // sorted pos -> sample-space pos

// KNN results, keyed by SAMPLE-SPACE position s (only sampled rows are consumed)
__device__ int    g_aidx[BB * SS * 4];  // full-space top-4: values = global ids
__device__ float  g_adist[BB * SS * 4];
__device__ int    g_saidx[BB * SS * 4]; // sampled-space top-4: values = sample-space pos
__device__ float  g_sadist[BB * SS * 4];

// ---------------- helpers ----------------
__device__ __forceinline__ void insert4f(float (&bd)[4], int (&bi)[4], float d, int j) {
    if (d >= bd[3]) return;
    if (d < bd[2]) {
        bd[3] = bd[2]; bi[3] = bi[2];
        if (d < bd[1]) {
            bd[2] = bd[1]; bi[2] = bi[1];
            if (d < bd[0]) {
                bd[1] = bd[0]; bi[1] = bi[0];
                bd[0] = d; bi[0] = j;
            } else { bd[1] = d; bi[1] = j; }
        } else { bd[2] = d; bi[2] = j; }
    } else { bd[3] = d; bi[3] = j; }
}

// ---------------- K0: pack xyz + squared norm ----------------
__global__ void k_prep(const float* __restrict__ xyz) {
    int i = blockIdx.x * blockDim.x + threadIdx.x;
    if (i >= BB * NN) return;
    float x = xyz[3 * i], y = xyz[3 * i + 1], z = xyz[3 * i + 2];
    float sq = fmaf(x, x, fmaf(y, y, z * z));
    g_xyzw[i] = make_float4(x, y, z, sq);
}

// ---------------- K0b: gather sampled points, emit sampled_xyz output ----------------
__global__ void k_gather(const int* __restrict__ sample, float* __restrict__ out) {
    int i = blockIdx.x * blockDim.x + threadIdx.x;
    if (i >= BB * SS) return;
    int b = i / SS;
    int g = sample[i];
    float4 v = g_xyzw[b * NN + g];
    g_sxyzw[i] = v;
    out[3 * i + 0] = v.x;
    out[3 * i + 1] = v.y;
    out[3 * i + 2] = v.z;
}

// ---------------- K1: bitonic z-sort; device globals referenced DIRECTLY ----------------
// (passing __device__ symbols as host-side kernel args reads the host shadow
//  copy via ATS on GB300 — silent corruption. Round-2 bug.)
template <bool FULL>
__global__ __launch_bounds__(1024) void k_sort() {
    constexpr int M = FULL ? NN : SS;
    extern __shared__ unsigned long long keys[];
    const int b = blockIdx.x;
    const float4* pts = (FULL ? g_xyzw : g_sxyzw) + b * M;
    float4* sp = (FULL ? g_pfull : g_psamp);
    float*  sz = (FULL ? g_zfull : g_zsamp);
    int*    so = (FULL ? g_ofull : g_osamp);
    const int t = threadIdx.x;

    for (int i = t; i < M; i += 1024) {
        unsigned bits = __float_as_uint(pts[i].z);
        bits = (bits & 0x80000000u) ? ~bits : (bits | 0x80000000u);
        keys[i] = ((unsigned long long)bits << 32) | (unsigned)i;
    }
    __syncthreads();

    for (int k = 2; k <= M; k <<= 1) {
        for (int j = k >> 1; j > 0; j >>= 1) {
            for (int i = t; i < M; i += 1024) {
                int p = i ^ j;
                if (p > i) {
                    unsigned long long a = keys[i], c = keys[p];
                    bool up = ((i & k) == 0);
                    if ((a > c) == up) { keys[i] = c; keys[p] = a; }
                }
            }
            __syncthreads();
        }
    }

    for (int i = t; i < M; i += 1024) {
        int idx = (int)(keys[i] & 0xffffffffu);
        float4 v = pts[idx];
        sp[b * M + i] = v;
        sz[b * M + i] = v.z;
        so[b * M + i] = idx;
    }
}

// ---------------- pruned two-sided scan: warp-collective top-4 ----------------
__device__ __forceinline__ void knn_scan(const float4 qp,
                                         const float*  __restrict__ zz,
                                         const float4* __restrict__ pts,
                                         int M, int start, int lane,
                                         float (&bd)[4], int (&bi)[4]) {
    int ptrL = start, ptrR = start;
    while (true) {
        bool canL = ptrL > 0, canR = ptrR < M;
        if (!canL && !canR) break;
        float dzL = canL ? (qp.z - zz[ptrL - 1]) : CUDART_INF_F;
        float dzR = canR ? (zz[ptrR] - qp.z)     : CUDART_INF_F;
        // warp-wide conservative threshold: min over lanes of per-lane 4th-best
        float thr = bd[3];
        #pragma unroll
        for (int off = 16; off; off >>= 1)
            thr = fminf(thr, __shfl_xor_sync(0xffffffffu, thr, off));
        float mdz = fminf(dzL, dzR);
        if (mdz * mdz > thr) break;   // no remaining candidate can enter top-4
        bool takeR = (dzR <= dzL);
        int base;
        if (takeR) { base = ptrR; ptrR += 32; }
        else       { base = ptrL - 32; ptrL -= 32; }
        int idx = base + lane;
        if (idx >= 0 && idx < M) {
            float4 c = pts[idx];
            float dot = fmaf(qp.x, c.x, fmaf(qp.y, c.y, qp.z * c.z));
            float d2  = fmaxf(qp.w + c.w - 2.0f * dot, 1e-12f);
            insert4f(bd, bi, d2, idx);
        }
    }
    // butterfly merge of sorted top-4 lists across warp
    #pragma unroll
    for (int off = 16; off; off >>= 1) {
        float od[4]; int oi[4];
        #pragma unroll
        for (int k = 0; k < 4; k++) {
            od[k] = __shfl_xor_sync(0xffffffffu, bd[k], off);
            oi[k] = __shfl_xor_sync(0xffffffffu, bi[k], off);
        }
        #pragma unroll
        for (int k = 0; k < 4; k++) insert4f(bd, bi, od[k], oi[k]);
    }
}

// ---------------- K2: full-space KNN, queries = sampled points only ----------------
__global__ __launch_bounds__(256) void k_knn_full() {
    const int b    = blockIdx.y;
    const int warp = threadIdx.x >> 5;
    const int lane = threadIdx.x & 31;
    const int r    = blockIdx.x * 8 + warp;      // rank in z-sorted sampled array

    const float4* pts = g_pfull + b * NN;
    const float*  zz  = g_zfull + b * NN;
    const float4  qp  = g_psamp[b * SS + r];

    // lower_bound of qp.z in full sorted z (warp-uniform)
    int lo = 0, hi = NN;
    while (lo < hi) { int mid = (lo + hi) >> 1; if (zz[mid] < qp.z) lo = mid + 1; else hi = mid; }

    float bd[4] = {CUDART_INF_F, CUDART_INF_F, CUDART_INF_F, CUDART_INF_F};
    int   bi[4] = {0, 0, 0, 0};
    knn_scan(qp, zz, pts, NN, lo, lane, bd, bi);

    if (lane == 0) {
        int s = g_osamp[b * SS + r];             // sample-space position
        #pragma unroll
        for (int k = 0; k < 4; k++) {
            g_aidx [(b * SS + s) * 4 + k] = g_ofull[b * NN + bi[k]];  // global id
            g_adist[(b * SS + s) * 4 + k] = sqrtf(bd[k]);
        }
    }
}

// ---------------- K3: sampled-space KNN ----------------
__global__ __launch_bounds__(256) void k_knn_samp() {
    const int b    = blockIdx.y;
    const int warp = threadIdx.x >> 5;
    const int lane = threadIdx.x & 31;
    const int r    = blockIdx.x * 8 + warp;      // rank in z-sorted sampled array

    const float4* pts = g_psamp + b * SS;
    const float*  zz  = g_zsamp + b * SS;
    const float4  qp  = pts[r];

    float bd[4] = {CUDART_INF_F, CUDART_INF_F, CUDART_INF_F, CUDART_INF_F};
    int   bi[4] = {0, 0, 0, 0};
    knn_scan(qp, zz, pts, SS, r, lane, bd, bi);

    if (lane == 0) {
        int s = g_osamp[b * SS + r];
        #pragma unroll
        for (int k = 0; k < 4; k++) {
            g_saidx [(b * SS + s) * 4 + k] = g_osamp[b * SS + bi[k]]; // sample-space pos
            g_sadist[(b * SS + s) * 4 + k] = sqrtf(bd[k]);
        }
    }
}

// ---------------- K4: fused 28-feature build + 3-layer MLP ----------------
__global__ __launch_bounds__(128) void k_fused(
    const float* __restrict__ feature,
    const int*   __restrict__ sample,
    const float* __restrict__ w1, const float* __restrict__ b1,
    const float* __restrict__ g1, const float* __restrict__ be1,
    const float* __restrict__ w2, const float* __restrict__ b2,
    const float* __restrict__ g2, const float* __restrict__ be2,
    const float* __restrict__ w3, const float* __restrict__ b3,
    const float* __restrict__ g3, const float* __restrict__ be3,
    float* __restrict__ out)
{
    __shared__ float x28[TP][28];
    __shared__ float t1s[TP][64];
    __shared__ float in2[TP][128];
    __shared__ int sp_g[TP];
    __shared__ int sp_a[TP][4];   // global anchor indices (before)
    __shared__ int sp_ga[TP][4];  // global indices of sampled anchors (after)

    const int tid = threadIdx.x;
    const int blk = blockIdx.x;
    const int b   = blk / (SS / TP);
    const int s0  = (blk % (SS / TP)) * TP;

    if (tid < TP) {
        int p = tid;
        int s = s0 + p;
        int g = sample[b * SS + s];
        sp_g[p] = g;
        #pragma unroll
        for (int k = 0; k < 4; k++) {
            sp_a[p][k] = g_aidx[(b * SS + s) * 4 + k];
            int sa = g_saidx[(b * SS + s) * 4 + k];
            sp_ga[p][k] = sample[b * SS + sa];
        }
        #pragma unroll
        for (int k = 0; k < 3; k++) {
            x28[p][k]     = g_adist[(b * SS + s) * 4 + 1 + k];   // intra_before ch 0..2
            x28[p][6 + k] = g_sadist[(b * SS + s) * 4 + 1 + k];  // intra_after  ch 6..8
        }
    }
    __syncthreads();

    // 22 fresh distances per point: ch 3..5, 9..11, 12..27
    for (int t = tid; t < TP * 22; t += 128) {
        int p = t / 22, w = t % 22;
        int ia, ib, ch;
        if (w < 3) {                 // pairs among a1..a3: (1,2)(1,3)(2,3)
            int pi = (w < 2) ? 1 : 2;
            int pj = (w == 0) ? 2 : 3;
            ia = sp_a[p][pi]; ib = sp_a[p][pj]; ch = 3 + w;
        } else if (w < 6) {          // pairs among ga1..ga3
            int u = w - 3;
            int pi = (u < 2) ? 1 : 2;
            int pj = (u == 0) ? 2 : 3;
            ia = sp_ga[p][pi]; ib = sp_ga[p][pj]; ch = 9 + u;
        } else {                     // inter: i-major over anchors_before, j over anchors_after
            int u = w - 6;
            int i = u >> 2, j = u & 3;
            ia = sp_a[p][i]; ib = sp_ga[p][j]; ch = 12 + u;
        }
        float4 pa = g_xyzw[b * NN + ia];
        float4 pb = g_xyzw[b * NN + ib];
        float dot = fmaf(pa.x, pb.x, fmaf(pa.y, pb.y, pa.z * pb.z));
        float d2 = fmaxf(pa.w + pb.w - 2.0f * dot, 1e-12f);
        x28[p][ch] = sqrtf(d2);
    }

    // gather sampled features into in2[p][0..63]
    for (int t = tid; t < TP * 64; t += 128) {
        int p = t >> 6, c = t & 63;
        in2[p][c] = feature[(size_t)(b * NN + sp_g[p]) * IN_CH + c];
    }
    __syncthreads();

    const float invs = 1.0f / sqrtf(1.0f + 1e-5f);

    // layer 1: 28 -> 64
    if (tid < 64) {
        float acc[TP];
        #pragma unroll
        for (int p = 0; p < TP; p++) acc[p] = b1[tid];
        #pragma unroll
        for (int k = 0; k < 28; k++) {
            float w = w1[k * 64 + tid];
            #pragma unroll
            for (int p = 0; p < TP; p++) acc[p] = fmaf(x28[p][k], w, acc[p]);
        }
        float sc = g1[tid] * invs, sh = be1[tid];
        #pragma unroll
        for (int p = 0; p < TP; p++) {
            float v = fmaf(acc[p], sc, sh);
            t1s[p][tid] = (v >= 0.0f) ? v : 0.2f * v;
        }
    }
    __syncthreads();

    // layer 2: 64 -> 64, output into in2[p][64..127]
    if (tid < 64) {
        float acc[TP];
        #pragma unroll
        for (int p = 0; p < TP; p++) acc[p] = b2[tid];
        #pragma unroll
        for (int k = 0; k < 64; k++) {
            float w = w2[k * 64 + tid];
            #pragma unroll
            for (int p = 0; p < TP; p++) acc[p] = fmaf(t1s[p][k], w, acc[p]);
        }
        float sc = g2[tid] * invs, sh = be2[tid];
        #pragma unroll
        for (int p = 0; p < TP; p++) {
            float v = fmaf(acc[p], sc, sh);
            in2[p][64 + tid] = (v >= 0.0f) ? v : 0.2f * v;
        }
    }
    __syncthreads();

    // layer 3: 128 -> 128
    {
        float acc[TP];
        #pragma unroll
        for (int p = 0; p < TP; p++) acc[p] = b3[tid];
        #pragma unroll
        for (int k = 0; k < 128; k++) {
            float w = w3[k * 128 + tid];
            #pragma unroll
            for (int p = 0; p < TP; p++) acc[p] = fmaf(in2[p][k], w, acc[p]);
        }
        float sc = g3[tid] * invs, sh = be3[tid];
        const size_t obase = (size_t)BB * SS * 3;
        #pragma unroll
        for (int p = 0; p < TP; p++) {
            float v = fmaf(acc[p], sc, sh);
            v = (v >= 0.0f) ? v : 0.2f * v;
            out[obase + (size_t)((b * SS + s0 + p)) * OUT_CH + tid] = v;
        }
    }
}

// ---------------- launch ----------------
extern "C" void kernel_launch(void* const* d_in, const int* in_sizes, int n_in,
                              void* d_out, int out_size) {
    const float* xyz     = (const float*)d_in[0];
    const float* feature = (const float*)d_in[1];
    const int*   sample  = (const int*)d_in[2];
    const float* w1  = (const float*)d_in[3];
    const float* b1  = (const float*)d_in[4];
    const float* g1  = (const float*)d_in[5];
    const float* be1 = (const float*)d_in[6];
    const float* w2  = (const float*)d_in[7];
    const float* b2  = (const float*)d_in[8];
    const float* g2  = (const float*)d_in[9];
    const float* be2 = (const float*)d_in[10];
    const float* w3  = (const float*)d_in[11];
    const float* b3  = (const float*)d_in[12];
    const float* g3  = (const float*)d_in[13];
    const float* be3 = (const float*)d_in[14];
    float* out = (float*)d_out;

    // opt-in dynamic smem for the 64KB sort (host-side attribute, idempotent)
    cudaFuncSetAttribute(k_sort<true>,  cudaFuncAttributeMaxDynamicSharedMemorySize, NN * 8);
    cudaFuncSetAttribute(k_sort<false>, cudaFuncAttributeMaxDynamicSharedMemorySize, SS * 8);

    k_prep<<<(BB * NN + 255) / 256, 256>>>(xyz);
    k_gather<<<(BB * SS + 255) / 256, 256>>>(sample, out);

    k_sort<true><<<BB, 1024, NN * 8>>>();
    k_sort<false><<<BB, 1024, SS * 8>>>();

    dim3 gk(SS / 8, BB);
    k_knn_full<<<gk, 256>>>();
    k_knn_samp<<<gk, 256>>>();

    k_fused<<<BB * SS / TP, 128>>>(feature, sample,
                                   w1, b1, g1, be1,
                                   w2, b2, g2, be2,
                                   w3, b3, g3, be3,
                                   out);
}